// round 1
// baseline (speedup 1.0000x reference)
#include <cuda_runtime.h>
#include <math.h>

#define NN   8192
#define DD   200
#define BB   4
#define EE   4096
#define DEG  16
#define HH   128
#define EPSf 1e-8f

// ---------------- scratch (device globals; no allocation allowed) ----------------
__device__ float g_out[NN * DD];      // x @ W
__device__ float g_hyper[NN * DD];    // L @ out
__device__ float g_Medge[EE * DD];    // (de/256) * sum_{n in e} dv[n]*out[n,:]
__device__ float g_gp[NN * HH];
__device__ float g_fused[NN * HH];
__device__ int   g_dv_cnt[NN];        // # edges containing node (deduped)
__device__ int   g_cursor[NN];
__device__ int   g_de_cnt[EE];        // # unique nodes in edge
__device__ unsigned g_maskbits[EE];   // first-occurrence mask per edge slot
__device__ int   g_offsets[NN];       // CSR row starts
__device__ int   g_node_edges[EE * DEG];
__device__ float g_alpha_part[256];
__device__ float g_alpha;
__device__ float g_att[BB * HH];      // per-batch constant attention output
__device__ float g_cvec[BB * HH];     // att @ fgate_w[H:2H] + fgate_b

// ---------------- misc small kernels ----------------
__global__ void k_zero() {
    int i = blockIdx.x * blockDim.x + threadIdx.x;
    if (i < NN) { g_dv_cnt[i] = 0; g_cursor[i] = 0; }
}

// partial sums of sum_{n,d} x[n,d]*gate_w[d]
__global__ void k_alpha_part(const float* __restrict__ x, const float* __restrict__ gw) {
    __shared__ float sm[256];
    int t = threadIdx.x;
    float s = 0.f;
    for (int i = blockIdx.x * 256 + t; i < NN * DD; i += 256 * 256)
        s += x[i] * gw[i % DD];
    sm[t] = s; __syncthreads();
    for (int o = 128; o > 0; o >>= 1) { if (t < o) sm[t] += sm[t + o]; __syncthreads(); }
    if (t == 0) g_alpha_part[blockIdx.x] = sm[0];
}

__global__ void k_alpha_fin(const float* __restrict__ gb) {
    __shared__ float sm[256];
    int t = threadIdx.x;
    sm[t] = g_alpha_part[t]; __syncthreads();
    for (int o = 128; o > 0; o >>= 1) { if (t < o) sm[t] += sm[t + o]; __syncthreads(); }
    if (t == 0) g_alpha = 1.f / (1.f + expf(-(sm[0] / (float)NN + gb[0])));
}

// ---------------- hypergraph sparse stages ----------------
// per-edge dedup: mask of first occurrences, unique count, node degree counts
__global__ void k_edge_a(const int* __restrict__ en) {
    int e = blockIdx.x * blockDim.x + threadIdx.x;
    if (e >= EE) return;
    int nd[DEG];
#pragma unroll
    for (int s = 0; s < DEG; s++) nd[s] = en[e * DEG + s];
    unsigned m = 0; int uniq = 0;
#pragma unroll
    for (int s = 0; s < DEG; s++) {
        bool first = true;
        for (int j = 0; j < s; j++) if (nd[j] == nd[s]) { first = false; break; }
        if (first) { m |= (1u << s); uniq++; atomicAdd(&g_dv_cnt[nd[s]], 1); }
    }
    g_maskbits[e] = m;
    g_de_cnt[e] = uniq;
}

// exclusive scan of g_dv_cnt -> g_offsets (single block, deterministic)
__global__ void k_scan() {
    __shared__ int part[256];
    int t = threadIdx.x;
    int base = t * 32;
    int s = 0;
    for (int i = 0; i < 32; i++) s += g_dv_cnt[base + i];
    part[t] = s; __syncthreads();
    for (int off = 1; off < 256; off <<= 1) {
        int v = 0;
        if (t >= off) v = part[t - off];
        __syncthreads();
        part[t] += v;
        __syncthreads();
    }
    int run = (t == 0) ? 0 : part[t - 1];
    for (int i = 0; i < 32; i++) { g_offsets[base + i] = run; run += g_dv_cnt[base + i]; }
}

__global__ void k_fill(const int* __restrict__ en) {
    int e = blockIdx.x * blockDim.x + threadIdx.x;
    if (e >= EE) return;
    unsigned m = g_maskbits[e];
    for (int s = 0; s < DEG; s++) if ((m >> s) & 1u) {
        int n = en[e * DEG + s];
        int p = atomicAdd(&g_cursor[n], 1);
        g_node_edges[g_offsets[n] + p] = e;
    }
}

// sort each node's edge list for a deterministic FP accumulation order
__global__ void k_sort() {
    int n = blockIdx.x * blockDim.x + threadIdx.x;
    if (n >= NN) return;
    int len = g_dv_cnt[n];
    int* a = &g_node_edges[g_offsets[n]];
    for (int i = 1; i < len; i++) {
        int key = a[i]; int j = i - 1;
        while (j >= 0 && a[j] > key) { a[j + 1] = a[j]; j--; }
        a[j + 1] = key;
    }
}

// M_edge[e,:] = (de[e]/256) * sum_{unique n in e} dv[n]*out[n,:]
__global__ void k_edge_b(const int* __restrict__ en) {
    int e = blockIdx.x;
    __shared__ int   sn[DEG];
    __shared__ float sw[DEG];
    int t = threadIdx.x;
    if (t < DEG) {
        int n = en[e * DEG + t];
        sn[t] = n;
        sw[t] = ((g_maskbits[e] >> t) & 1u)
                  ? rsqrtf((float)g_dv_cnt[n] * (1.f / DEG) + EPSf) : 0.f;
    }
    __syncthreads();
    if (t >= DD) return;
    float acc = 0.f;
#pragma unroll
    for (int s = 0; s < DEG; s++) acc += sw[s] * g_out[sn[s] * DD + t];
    float de_inv = 1.f / ((float)g_de_cnt[e] * (1.f / DEG) + EPSf);
    g_Medge[e * DD + t] = acc * de_inv * (1.f / (DEG * DEG));
}

// hyper[n,:] = dv[n] * sum_{e in csr(n)} M_edge[e,:]
__global__ void k_gather() {
    int n = blockIdx.x;
    int t = threadIdx.x;
    int len  = g_dv_cnt[n];
    int base = g_offsets[n];
    float dvn = rsqrtf((float)len * (1.f / DEG) + EPSf);
    if (t >= DD) return;
    float acc = 0.f;
    for (int i = 0; i < len; i++) {
        int e = g_node_edges[base + i];
        acc += g_Medge[e * DD + t];
    }
    g_hyper[n * DD + t] = dvn * acc;
}

// ---------------- per-batch constants (attention collapses: softmax over len-1 == 1) ----------------
__global__ void k_const(const float* __restrict__ text,
                        const float* __restrict__ text_w, const float* __restrict__ text_b,
                        const float* __restrict__ in_w,   const float* __restrict__ in_b,
                        const float* __restrict__ aow,    const float* __restrict__ aob,
                        const float* __restrict__ fgw,    const float* __restrict__ fgb) {
    __shared__ float tp[BB][HH];
    __shared__ float vv[BB][HH];
    __shared__ float at[BB][HH];
    int j = threadIdx.x;  // 128 threads
    for (int b = 0; b < BB; b++) {
        float s = text_b[j];
        for (int k = 0; k < DD; k++) s += text[b * DD + k] * text_w[k * HH + j];
        tp[b][j] = s;
    }
    __syncthreads();
    for (int b = 0; b < BB; b++) {
        float s = in_b[2 * HH + j];
        for (int k = 0; k < HH; k++) s += tp[b][k] * in_w[k * 3 * HH + 2 * HH + j];
        vv[b][j] = s;
    }
    __syncthreads();
    for (int b = 0; b < BB; b++) {
        float s = aob[j];
        for (int k = 0; k < HH; k++) s += vv[b][k] * aow[k * HH + j];
        at[b][j] = s;
        g_att[b * HH + j] = s;
    }
    __syncthreads();
    for (int b = 0; b < BB; b++) {
        float s = fgb[j];
        for (int k = 0; k < HH; k++) s += at[b][k] * fgw[(HH + k) * HH + j];
        g_cvec[b * HH + j] = s;
    }
}

// ---------------- tiled SGEMM with fused A-generation / epilogues ----------------
// MODE 0: g_out   = Aext @ Bm                      (x @ W)
// MODE 1: g_gp    = (alpha*g_out+(1-a)*g_hyper+avec[k]) @ Bm + bias   (gnn proj)
// MODE 2: g_fused = gate-fusion epilogue of (g_gp @ Bm)               (fgate rows 0..H-1)
// MODE 3: Cext    = g_fused @ Bm + bias            (output proj)
template <int MODE>
__global__ void gemm_k(const float* __restrict__ Aext, const float* __restrict__ Bm,
                       float* __restrict__ Cext, int M, int Ncols, int K,
                       const float* __restrict__ bias, const float* __restrict__ avec) {
    const float* A = (MODE == 1) ? (const float*)g_out
                   : (MODE == 2) ? (const float*)g_gp
                   : (MODE == 3) ? (const float*)g_fused : Aext;
    float* C = (MODE == 0) ? (float*)g_out
             : (MODE == 1) ? (float*)g_gp
             : (MODE == 2) ? (float*)g_fused : Cext;

    __shared__ __align__(16) float As[16][68];   // transposed: As[k][m]
    __shared__ __align__(16) float Bs[16][64];

    const int t  = threadIdx.x;
    const int tx = t & 15, ty = t >> 4;
    const int m0 = blockIdx.y * 64;
    const int n0 = blockIdx.x * 64;

    float alpha = 0.f, beta = 0.f;
    if (MODE == 1) { alpha = g_alpha; beta = 1.f - alpha; }

    float acc[4][4];
#pragma unroll
    for (int i = 0; i < 4; i++)
#pragma unroll
        for (int j = 0; j < 4; j++) acc[i][j] = 0.f;

    const int arow = t >> 2;
    const int kq   = (t & 3) * 4;
    const int brow = t >> 4;
    const int bcol = (t & 15) * 4;
    const int KB = (K + 15) / 16;

    for (int kb = 0; kb < KB; kb++) {
        int k0 = kb * 16;
        {   // A tile (store transposed)
            int grow = m0 + arow;
            int base = grow * K;
#pragma unroll
            for (int c = 0; c < 4; c++) {
                int gk = k0 + kq + c;
                float v = 0.f;
                if (gk < K) {
                    if (MODE == 1)
                        v = alpha * A[base + gk] + beta * g_hyper[base + gk] + avec[gk];
                    else
                        v = A[base + gk];
                }
                As[kq + c][arow] = v;
            }
        }
        {   // B tile
            int gk = k0 + brow;
#pragma unroll
            for (int c = 0; c < 4; c++) {
                int gn = n0 + bcol + c;
                float v = 0.f;
                if (gk < K && gn < Ncols) v = Bm[gk * Ncols + gn];
                Bs[brow][bcol + c] = v;
            }
        }
        __syncthreads();
#pragma unroll
        for (int kk = 0; kk < 16; kk++) {
            float4 a4 = *(const float4*)&As[kk][ty * 4];
            float4 b4 = *(const float4*)&Bs[kk][tx * 4];
            float ar[4] = {a4.x, a4.y, a4.z, a4.w};
            float br[4] = {b4.x, b4.y, b4.z, b4.w};
#pragma unroll
            for (int i = 0; i < 4; i++)
#pragma unroll
                for (int j = 0; j < 4; j++) acc[i][j] += ar[i] * br[j];
        }
        __syncthreads();
    }

#pragma unroll
    for (int i = 0; i < 4; i++) {
        int r = m0 + ty * 4 + i;
#pragma unroll
        for (int j = 0; j < 4; j++) {
            int cidx = n0 + tx * 4 + j;
            if (cidx >= Ncols) continue;
            float v = acc[i][j];
            if (MODE == 0) {
                C[r * Ncols + cidx] = v;
            } else if (MODE == 1 || MODE == 3) {
                C[r * Ncols + cidx] = v + bias[cidx];
            } else {  // MODE 2: sigmoid gate + convex fuse (att is per-batch constant)
                int bi = r >> 11;  // Nn = 2048
                float g = 1.f / (1.f + expf(-(v + g_cvec[bi * HH + cidx])));
                float gpv  = A[r * K + cidx];          // K == HH here
                float attv = g_att[bi * HH + cidx];
                C[r * Ncols + cidx] = g * gpv + (1.f - g) * attv;
            }
        }
    }
}

// ---------------- launcher ----------------
extern "C" void kernel_launch(void* const* d_in, const int* in_sizes, int n_in,
                              void* d_out, int out_size) {
    const float* x      = (const float*)d_in[0];
    const float* text   = (const float*)d_in[1];
    const float* W      = (const float*)d_in[2];
    const float* bvec   = (const float*)d_in[3];
    const float* gate_w = (const float*)d_in[4];
    const float* gate_b = (const float*)d_in[5];
    const float* gnn_w  = (const float*)d_in[6];
    const float* gnn_b  = (const float*)d_in[7];
    const float* text_w = (const float*)d_in[8];
    const float* text_b = (const float*)d_in[9];
    const float* in_w   = (const float*)d_in[10];
    const float* in_b   = (const float*)d_in[11];
    const float* aow    = (const float*)d_in[12];
    const float* aob    = (const float*)d_in[13];
    const float* fgw    = (const float*)d_in[14];
    const float* fgb    = (const float*)d_in[15];
    const float* outp_w = (const float*)d_in[16];
    const float* outp_b = (const float*)d_in[17];
    const int*   en     = (const int*)d_in[18];
    float* outp = (float*)d_out;

    k_zero<<<32, 256>>>();
    k_alpha_part<<<256, 256>>>(x, gate_w);
    k_alpha_fin<<<1, 256>>>(gate_b);

    // out = x @ W
    gemm_k<0><<<dim3(4, 128), 256>>>(x, W, nullptr, NN, DD, DD, nullptr, nullptr);

    // hypergraph propagation
    k_edge_a<<<EE / 256, 256>>>(en);
    k_scan<<<1, 256>>>();
    k_fill<<<EE / 256, 256>>>(en);
    k_sort<<<NN / 256, 256>>>();
    k_edge_b<<<EE, 224>>>(en);
    k_gather<<<NN, 224>>>();

    // per-batch attention constants (independent path)
    k_const<<<1, 128>>>(text, text_w, text_b, in_w, in_b, aow, aob, fgw, fgb);

    // gp = (alpha*out + (1-alpha)*hyper + b) @ gnn_w + gnn_b
    gemm_k<1><<<dim3(2, 128), 256>>>(nullptr, gnn_w, nullptr, NN, HH, DD, gnn_b, bvec);

    // fused = sigmoid(gp @ fgate_w[:H] + c[b]) * gp + (1-g) * att[b]
    gemm_k<2><<<dim3(2, 128), 256>>>(nullptr, fgw, nullptr, NN, HH, HH, nullptr, nullptr);

    // result = fused @ outp_w + outp_b
    gemm_k<3><<<dim3(4, 128), 256>>>(nullptr, outp_w, outp, NN, DD, HH, outp_b, nullptr);
}

// round 2
// speedup vs baseline: 1.1481x; 1.1481x over previous
#include <cuda_runtime.h>
#include <math.h>

#define NN   8192
#define DD   200
#define BB   4
#define EE   4096
#define DEG  16
#define HH   128
#define EPSf 1e-8f

// ---------------- scratch (device globals; no allocation allowed) ----------------
__device__ float g_out[NN * DD];      // x @ W
__device__ float g_hyper[NN * DD];    // L @ out
__device__ float g_Medge[EE * DD];
__device__ float g_gp[NN * HH];
__device__ float g_fused[NN * HH];
__device__ int   g_dv_cnt[NN];
__device__ int   g_cursor[NN];
__device__ int   g_de_cnt[EE];
__device__ unsigned g_maskbits[EE];
__device__ int   g_offsets[NN];
__device__ int   g_node_edges[EE * DEG];
__device__ float g_alpha_part[256];
__device__ float g_alpha;
__device__ float g_att[BB * HH];
__device__ float g_cvec[BB * HH];

// ---------------- misc small kernels ----------------
__global__ void k_zero() {
    int i = blockIdx.x * blockDim.x + threadIdx.x;
    if (i < NN) { g_dv_cnt[i] = 0; g_cursor[i] = 0; }
}

__global__ void k_alpha_part(const float* __restrict__ x, const float* __restrict__ gw) {
    __shared__ float sm[256];
    int t = threadIdx.x;
    float s = 0.f;
    for (int i = blockIdx.x * 256 + t; i < NN * DD; i += 256 * 256)
        s += x[i] * gw[i % DD];
    sm[t] = s; __syncthreads();
    for (int o = 128; o > 0; o >>= 1) { if (t < o) sm[t] += sm[t + o]; __syncthreads(); }
    if (t == 0) g_alpha_part[blockIdx.x] = sm[0];
}

__global__ void k_alpha_fin(const float* __restrict__ gb) {
    __shared__ float sm[256];
    int t = threadIdx.x;
    sm[t] = g_alpha_part[t]; __syncthreads();
    for (int o = 128; o > 0; o >>= 1) { if (t < o) sm[t] += sm[t + o]; __syncthreads(); }
    if (t == 0) g_alpha = 1.f / (1.f + expf(-(sm[0] / (float)NN + gb[0])));
}

// ---------------- hypergraph sparse stages ----------------
__global__ void k_edge_a(const int* __restrict__ en) {
    int e = blockIdx.x * blockDim.x + threadIdx.x;
    if (e >= EE) return;
    int nd[DEG];
#pragma unroll
    for (int s = 0; s < DEG; s++) nd[s] = en[e * DEG + s];
    unsigned m = 0; int uniq = 0;
#pragma unroll
    for (int s = 0; s < DEG; s++) {
        bool first = true;
        for (int j = 0; j < s; j++) if (nd[j] == nd[s]) { first = false; break; }
        if (first) { m |= (1u << s); uniq++; atomicAdd(&g_dv_cnt[nd[s]], 1); }
    }
    g_maskbits[e] = m;
    g_de_cnt[e] = uniq;
}

__global__ void k_scan() {
    __shared__ int part[256];
    int t = threadIdx.x;
    int base = t * 32;
    int s = 0;
    for (int i = 0; i < 32; i++) s += g_dv_cnt[base + i];
    part[t] = s; __syncthreads();
    for (int off = 1; off < 256; off <<= 1) {
        int v = 0;
        if (t >= off) v = part[t - off];
        __syncthreads();
        part[t] += v;
        __syncthreads();
    }
    int run = (t == 0) ? 0 : part[t - 1];
    for (int i = 0; i < 32; i++) { g_offsets[base + i] = run; run += g_dv_cnt[base + i]; }
}

__global__ void k_fill(const int* __restrict__ en) {
    int e = blockIdx.x * blockDim.x + threadIdx.x;
    if (e >= EE) return;
    unsigned m = g_maskbits[e];
    for (int s = 0; s < DEG; s++) if ((m >> s) & 1u) {
        int n = en[e * DEG + s];
        int p = atomicAdd(&g_cursor[n], 1);
        g_node_edges[g_offsets[n] + p] = e;
    }
}

__global__ void k_sort() {
    int n = blockIdx.x * blockDim.x + threadIdx.x;
    if (n >= NN) return;
    int len = g_dv_cnt[n];
    int* a = &g_node_edges[g_offsets[n]];
    for (int i = 1; i < len; i++) {
        int key = a[i]; int j = i - 1;
        while (j >= 0 && a[j] > key) { a[j + 1] = a[j]; j--; }
        a[j + 1] = key;
    }
}

// M_edge[e,:] via float4 over DD=200 (50 float4)
__global__ void k_edge_b(const int* __restrict__ en) {
    int e = blockIdx.x;
    __shared__ int   sn[DEG];
    __shared__ float sw[DEG];
    int t = threadIdx.x;
    if (t < DEG) {
        int n = en[e * DEG + t];
        sn[t] = n;
        sw[t] = ((g_maskbits[e] >> t) & 1u)
                  ? rsqrtf((float)g_dv_cnt[n] * (1.f / DEG) + EPSf) : 0.f;
    }
    __syncthreads();
    if (t >= DD / 4) return;
    float4 acc = make_float4(0.f, 0.f, 0.f, 0.f);
#pragma unroll
    for (int s = 0; s < DEG; s++) {
        float w = sw[s];
        float4 v = ((const float4*)&g_out[sn[s] * DD])[t];
        acc.x += w * v.x; acc.y += w * v.y; acc.z += w * v.z; acc.w += w * v.w;
    }
    float sc = 1.f / ((float)g_de_cnt[e] * (1.f / DEG) + EPSf) * (1.f / (DEG * DEG));
    ((float4*)&g_Medge[e * DD])[t] =
        make_float4(acc.x * sc, acc.y * sc, acc.z * sc, acc.w * sc);
}

__global__ void k_gather() {
    int n = blockIdx.x;
    int t = threadIdx.x;
    int len  = g_dv_cnt[n];
    int base = g_offsets[n];
    float dvn = rsqrtf((float)len * (1.f / DEG) + EPSf);
    if (t >= DD / 4) return;
    float4 acc = make_float4(0.f, 0.f, 0.f, 0.f);
    for (int i = 0; i < len; i++) {
        int e = g_node_edges[base + i];
        float4 v = ((const float4*)&g_Medge[e * DD])[t];
        acc.x += v.x; acc.y += v.y; acc.z += v.z; acc.w += v.w;
    }
    ((float4*)&g_hyper[n * DD])[t] =
        make_float4(acc.x * dvn, acc.y * dvn, acc.z * dvn, acc.w * dvn);
}

// ---------------- per-batch constants ----------------
__global__ void k_const(const float* __restrict__ text,
                        const float* __restrict__ text_w, const float* __restrict__ text_b,
                        const float* __restrict__ in_w,   const float* __restrict__ in_b,
                        const float* __restrict__ aow,    const float* __restrict__ aob,
                        const float* __restrict__ fgw,    const float* __restrict__ fgb) {
    __shared__ float tp[BB][HH];
    __shared__ float vv[BB][HH];
    __shared__ float at[BB][HH];
    int j = threadIdx.x;  // 128 threads
    for (int b = 0; b < BB; b++) {
        float s = text_b[j];
        for (int k = 0; k < DD; k++) s += text[b * DD + k] * text_w[k * HH + j];
        tp[b][j] = s;
    }
    __syncthreads();
    for (int b = 0; b < BB; b++) {
        float s = in_b[2 * HH + j];
        for (int k = 0; k < HH; k++) s += tp[b][k] * in_w[k * 3 * HH + 2 * HH + j];
        vv[b][j] = s;
    }
    __syncthreads();
    for (int b = 0; b < BB; b++) {
        float s = aob[j];
        for (int k = 0; k < HH; k++) s += vv[b][k] * aow[k * HH + j];
        at[b][j] = s;
        g_att[b * HH + j] = s;
    }
    __syncthreads();
    for (int b = 0; b < BB; b++) {
        float s = fgb[j];
        for (int k = 0; k < HH; k++) s += at[b][k] * fgw[(HH + k) * HH + j];
        g_cvec[b * HH + j] = s;
    }
}

// ---------------- SGEMM v2: 64x64 tile, 128 threads, 8x4/thread, double-buffered ----------------
// MODE 0: g_out   = x @ W
// MODE 1: g_gp    = (alpha*g_out+(1-a)*g_hyper+avec) @ gnn_w + bias
// MODE 2: g_fused = gate-fusion epilogue of (g_gp @ fgate_w0)
// MODE 3: Cext    = g_fused @ outp_w + bias
#define ASTRIDE 68
template <int MODE>
__global__ void __launch_bounds__(128)
gemm2_k(const float* __restrict__ Aext, const float* __restrict__ Bm,
        float* __restrict__ Cext, int Ncols, int K,
        const float* __restrict__ bias, const float* __restrict__ avec) {
    const float* A = (MODE == 1) ? (const float*)g_out
                   : (MODE == 2) ? (const float*)g_gp
                   : (MODE == 3) ? (const float*)g_fused : Aext;
    float* C = (MODE == 0) ? (float*)g_out
             : (MODE == 1) ? (float*)g_gp
             : (MODE == 2) ? (float*)g_fused : Cext;

    __shared__ __align__(16) float AsT[2][16][ASTRIDE];  // [k][m]
    __shared__ __align__(16) float Bs [2][16][ASTRIDE];  // [k][n]

    const int t  = threadIdx.x;
    const int tx = t & 15;        // n-quad
    const int ty = t >> 4;        // m-oct
    const int m0 = blockIdx.y * 64;
    const int n0 = blockIdx.x * 64;

    float alpha = 0.f, beta = 0.f;
    if (MODE == 1) { alpha = g_alpha; beta = 1.f - alpha; }

    // A load mapping: 256 float4 per tile, 2 per thread
    const int aIdx0 = 2 * t, aIdx1 = 2 * t + 1;
    const int ar0 = aIdx0 >> 2, ak0 = (aIdx0 & 3) * 4;
    const int ar1 = aIdx1 >> 2, ak1 = (aIdx1 & 3) * 4;
    // B load mapping
    const int bk0 = aIdx0 >> 4, bn0 = (aIdx0 & 15) * 4;
    const int bk1 = aIdx1 >> 4, bn1 = (aIdx1 & 15) * 4;

    const int KB = (K + 15) / 16;

    float acc[8][4];
#pragma unroll
    for (int i = 0; i < 8; i++)
#pragma unroll
        for (int j = 0; j < 4; j++) acc[i][j] = 0.f;

    float4 ra0, ra1, rb0, rb1;
    const float4 z4 = make_float4(0.f, 0.f, 0.f, 0.f);

    auto loadChunk = [&](int k0) {
        // A
        int gk = k0 + ak0;
        if (gk < K) {
            int base = (m0 + ar0) * K + gk;
            if (MODE == 1) {
                float4 o = *(const float4*)&A[base];
                float4 h = *(const float4*)&g_hyper[base];
                float4 av = *(const float4*)&avec[gk];
                ra0 = make_float4(alpha*o.x + beta*h.x + av.x, alpha*o.y + beta*h.y + av.y,
                                  alpha*o.z + beta*h.z + av.z, alpha*o.w + beta*h.w + av.w);
            } else ra0 = *(const float4*)&A[base];
        } else ra0 = z4;
        gk = k0 + ak1;
        if (gk < K) {
            int base = (m0 + ar1) * K + gk;
            if (MODE == 1) {
                float4 o = *(const float4*)&A[base];
                float4 h = *(const float4*)&g_hyper[base];
                float4 av = *(const float4*)&avec[gk];
                ra1 = make_float4(alpha*o.x + beta*h.x + av.x, alpha*o.y + beta*h.y + av.y,
                                  alpha*o.z + beta*h.z + av.z, alpha*o.w + beta*h.w + av.w);
            } else ra1 = *(const float4*)&A[base];
        } else ra1 = z4;
        // B
        gk = k0 + bk0; int gn = n0 + bn0;
        rb0 = (gk < K && gn < Ncols) ? *(const float4*)&Bm[gk * Ncols + gn] : z4;
        gk = k0 + bk1; gn = n0 + bn1;
        rb1 = (gk < K && gn < Ncols) ? *(const float4*)&Bm[gk * Ncols + gn] : z4;
    };
    auto storeChunk = [&](int buf) {
        AsT[buf][ak0 + 0][ar0] = ra0.x; AsT[buf][ak0 + 1][ar0] = ra0.y;
        AsT[buf][ak0 + 2][ar0] = ra0.z; AsT[buf][ak0 + 3][ar0] = ra0.w;
        AsT[buf][ak1 + 0][ar1] = ra1.x; AsT[buf][ak1 + 1][ar1] = ra1.y;
        AsT[buf][ak1 + 2][ar1] = ra1.z; AsT[buf][ak1 + 3][ar1] = ra1.w;
        *(float4*)&Bs[buf][bk0][bn0] = rb0;
        *(float4*)&Bs[buf][bk1][bn1] = rb1;
    };

    loadChunk(0);
    storeChunk(0);
    __syncthreads();

    for (int kb = 0; kb < KB; kb++) {
        int buf = kb & 1;
        if (kb + 1 < KB) loadChunk((kb + 1) * 16);
#pragma unroll
        for (int kk = 0; kk < 16; kk++) {
            float4 a0 = *(const float4*)&AsT[buf][kk][ty * 8];
            float4 a1 = *(const float4*)&AsT[buf][kk][ty * 8 + 4];
            float4 b  = *(const float4*)&Bs[buf][kk][tx * 4];
            float am[8] = {a0.x, a0.y, a0.z, a0.w, a1.x, a1.y, a1.z, a1.w};
            float bn[4] = {b.x, b.y, b.z, b.w};
#pragma unroll
            for (int i = 0; i < 8; i++)
#pragma unroll
                for (int j = 0; j < 4; j++) acc[i][j] += am[i] * bn[j];
        }
        if (kb + 1 < KB) storeChunk(buf ^ 1);
        __syncthreads();
    }

    // epilogue
#pragma unroll
    for (int i = 0; i < 8; i++) {
        int r = m0 + ty * 8 + i;
        int cbase = n0 + tx * 4;
        if (MODE == 2) {
            if (cbase < Ncols) {
                int bi = r >> 11;  // Nn = 2048
                float4 gp4 = *(const float4*)&g_gp[r * HH + cbase];
                float gpv[4] = {gp4.x, gp4.y, gp4.z, gp4.w};
#pragma unroll
                for (int j = 0; j < 4; j++) {
                    int cidx = cbase + j;
                    float g = 1.f / (1.f + expf(-(acc[i][j] + g_cvec[bi * HH + cidx])));
                    float attv = g_att[bi * HH + cidx];
                    C[r * Ncols + cidx] = g * gpv[j] + (1.f - g) * attv;
                }
            }
        } else {
#pragma unroll
            for (int j = 0; j < 4; j++) {
                int cidx = cbase + j;
                if (cidx >= Ncols) continue;
                float v = acc[i][j];
                if (MODE != 0) v += bias[cidx];
                C[r * Ncols + cidx] = v;
            }
        }
    }
}

// ---------------- launcher ----------------
extern "C" void kernel_launch(void* const* d_in, const int* in_sizes, int n_in,
                              void* d_out, int out_size) {
    const float* x      = (const float*)d_in[0];
    const float* text   = (const float*)d_in[1];
    const float* W      = (const float*)d_in[2];
    const float* bvec   = (const float*)d_in[3];
    const float* gate_w = (const float*)d_in[4];
    const float* gate_b = (const float*)d_in[5];
    const float* gnn_w  = (const float*)d_in[6];
    const float* gnn_b  = (const float*)d_in[7];
    const float* text_w = (const float*)d_in[8];
    const float* text_b = (const float*)d_in[9];
    const float* in_w   = (const float*)d_in[10];
    const float* in_b   = (const float*)d_in[11];
    const float* aow    = (const float*)d_in[12];
    const float* aob    = (const float*)d_in[13];
    const float* fgw    = (const float*)d_in[14];
    const float* fgb    = (const float*)d_in[15];
    const float* outp_w = (const float*)d_in[16];
    const float* outp_b = (const float*)d_in[17];
    const int*   en     = (const int*)d_in[18];
    float* outp = (float*)d_out;

    k_zero<<<32, 256>>>();
    k_alpha_part<<<256, 256>>>(x, gate_w);
    k_alpha_fin<<<1, 256>>>(gate_b);

    // out = x @ W
    gemm2_k<0><<<dim3(4, 128), 128>>>(x, W, nullptr, DD, DD, nullptr, nullptr);

    // hypergraph propagation
    k_edge_a<<<EE / 256, 256>>>(en);
    k_scan<<<1, 256>>>();
    k_fill<<<EE / 256, 256>>>(en);
    k_sort<<<NN / 256, 256>>>();
    k_edge_b<<<EE, 64>>>(en);
    k_gather<<<NN, 64>>>();

    // per-batch attention constants
    k_const<<<1, 128>>>(text, text_w, text_b, in_w, in_b, aow, aob, fgw, fgb);

    // gp = (alpha*out + (1-alpha)*hyper + b) @ gnn_w + gnn_b
    gemm2_k<1><<<dim3(2, 128), 128>>>(nullptr, gnn_w, nullptr, HH, DD, gnn_b, bvec);

    // fused = sigmoid(gp @ fgate_w[:H] + c[b]) * gp + (1-g) * att[b]
    gemm2_k<2><<<dim3(2, 128), 128>>>(nullptr, fgw, nullptr, HH, HH, nullptr, nullptr);

    // result = fused @ outp_w + outp_b
    gemm2_k<3><<<dim3(4, 128), 128>>>(nullptr, outp_w, outp, DD, HH, outp_b, nullptr);
}